// round 16
// baseline (speedup 1.0000x reference)
#include <cuda_runtime.h>
#include <math.h>

#define Nn 100000
#define Ee 1600000
#define Dd 32
#define Kk 1024
#define HALF_E (Ee/2)
#define HALF_N (Nn/2)

#define PARTITIONABLE 1

#define GB   148
#define GBT  1024
#define GT   (GB * GBT)
#define CH   ((Nn + GB - 1) / GB)

#define CAND 2048

// ---------------- scratch ----------------
__device__ int      g_counts[Nn];        // zeroed initially + by finish each run
__device__ int      g_rowptr[Nn + 1];
__device__ int      g_pos[Ee];
__device__ __align__(16) float2 g_ecv[Ee]; // (col|dep<<28, v0) in EDGE order
__device__ __align__(16) int4   g_rec[Ee]; // (eid, pk, v0bits, 0) in CSR slot order
__device__ __align__(16) float2 g_cv[Ee];  // (pk, v0) in CSR sorted order
__device__ float    g_order0[Nn], g_order1[Nn], g_order2[Nn];
__device__ float    g_embA[Nn * Dd], g_embB[Nn * Dd], g_embS[Nn * Dd];
__device__ float    g_numA[Nn], g_numB[Nn], g_numS[Nn];
__device__ float    g_gumbel[Nn];
__device__ unsigned g_keys[Nn];
__device__ unsigned g_hist16[65536];     // zeroed by build each run
__device__ unsigned g_vbin;
__device__ int      g_cntG;
__device__ unsigned long long g_cand[CAND];
__device__ int      g_bsum[GB];
__device__ int      g_boff[GB];
__device__ unsigned g_bar[8];            // slots 0-4: build; 5-6: finish

// ---------------- threefry-2x32 (JAX schedule) ----------------
__host__ __device__ __forceinline__ void tf2x32(unsigned k0, unsigned k1,
                                                unsigned x0, unsigned x1,
                                                unsigned& o0, unsigned& o1) {
    unsigned k2 = k0 ^ k1 ^ 0x1BD11BDAu;
    x0 += k0; x1 += k1;
#define TFR(r) { x0 += x1; x1 = (x1 << r) | (x1 >> (32 - r)); x1 ^= x0; }
    TFR(13) TFR(15) TFR(26) TFR(6)   x0 += k1; x1 += k2 + 1u;
    TFR(17) TFR(29) TFR(16) TFR(24)  x0 += k2; x1 += k0 + 2u;
    TFR(13) TFR(15) TFR(26) TFR(6)   x0 += k0; x1 += k1 + 3u;
    TFR(17) TFR(29) TFR(16) TFR(24)  x0 += k1; x1 += k2 + 4u;
    TFR(13) TFR(15) TFR(26) TFR(6)   x0 += k2; x1 += k0 + 5u;
#undef TFR
    o0 = x0; o1 = x1;
}

__device__ __forceinline__ float bits_to_uniform(unsigned bits) {
    return __fsub_rn(__uint_as_float((bits >> 9) | 0x3f800000u), 1.0f);
}

__device__ __forceinline__ unsigned edge_bits(unsigned k0, unsigned k1, int e) {
#if PARTITIONABLE
    unsigned o0, o1;
    tf2x32(k0, k1, 0u, (unsigned)e, o0, o1);
    return o0 ^ o1;
#else
    unsigned o0, o1;
    if (e < HALF_E) { tf2x32(k0, k1, (unsigned)e, (unsigned)(e + HALF_E), o0, o1); return o0; }
    else            { tf2x32(k0, k1, (unsigned)(e - HALF_E), (unsigned)e, o0, o1); return o1; }
#endif
}

__device__ __forceinline__ float2 packcv(unsigned pk, float v) {
    float2 r; r.x = __uint_as_float(pk); r.y = v; return r;
}

// ---------------- accurate fp32 natural log (double-float, ~1e-10 rel) ----------------
__device__ float log_acc(float x) {
    if (x == 0.0f) return -INFINITY;
    if (isinf(x)) return INFINITY;
    int ix = __float_as_int(x);
    int e = ((ix >> 23) & 0xFF) - 127;
    float m = __int_as_float((ix & 0x007FFFFF) | 0x3F800000);
    if (m > 1.41421356f) { m *= 0.5f; e += 1; }
    float a = m - 1.0f;
    float bh = m + 1.0f;
    float bl;
    {
        float bp = bh - 1.0f;
        float ap = bh - bp;
        bl = (1.0f - ap) + (m - bp);
    }
    float q0 = a / bh;
    float r  = fmaf(-q0, bh, a);
    r = fmaf(-q0, bl, r);
    float q1 = r / bh;
    float th = q0 * q0;
    float tl = fmaf(q0, q0, -th);
    tl = fmaf(2.0f * q0, q1, tl);
    const float C3H = 0.333333343f;
    const float C3L = -9.93410830e-09f;
    float t2 = th * th;
    float tail = t2 * (0.2f + th * (0.14285714f + th * (0.11111111f +
                 th * (0.090909091f + th * 0.076923077f))));
    float Rh = th * C3H;
    float Rl = fmaf(th, C3H, -Rh);
    Rl += tl * C3H + th * C3L + tail;
    float twq0 = 2.0f * q0;
    float ph = twq0 * Rh;
    float pl = fmaf(twq0, Rh, -ph);
    pl += twq0 * Rl + 2.0f * q1 * Rh;
    float lh = twq0 + ph;
    float z = lh - twq0;
    float ll = (twq0 - (lh - z)) + (ph - z);
    ll += 2.0f * q1 + pl;
    const float LN2H = 0.693145751953125f;
    const float LN2L = 1.4286067653e-06f;
    float fe = (float)e;
    float eh = fe * LN2H;
    float el = fe * LN2L;
    float sh = eh + lh;
    float zz = sh - eh;
    float sl = (eh - (sh - zz)) + (lh - zz);
    return sh + (sl + el + ll);
}

// grid-wide barrier: all GB blocks co-resident (grid == #SMs, occ 1).
__device__ __forceinline__ void gridbar(int id) {
    __syncthreads();
    if (threadIdx.x == 0) {
        __threadfence();
        atomicAdd(&g_bar[id], 1u);
        while (*((volatile unsigned*)&g_bar[id]) < (unsigned)GB) { }
        __threadfence();
    }
    __syncthreads();
}

// ---------------- fused CSR build (+ gumbel) ----------------
__global__ void __launch_bounds__(GBT, 1) build_kernel(
        const int* __restrict__ rows, const int* __restrict__ cols,
        const float* __restrict__ adj,
        unsigned a0, unsigned a1, unsigned b0, unsigned b1,
        unsigned c0, unsigned c1) {
    int b = blockIdx.x, tid = threadIdx.x;
    int gt = b * GBT + tid;

    // Phase A: zero hist16; count (keep position); threefry keeps -> g_ecv; gumbel.
    for (int i = gt; i < 65536; i += GT) g_hist16[i] = 0u;
    for (int e = gt; e < Ee; e += GT) {
        int r = rows[e];
        g_pos[e] = atomicAdd(&g_counts[r], 1);
        unsigned bb0 = edge_bits(a0, a1, e);
        unsigned bb1 = edge_bits(b0, b1, e);
        unsigned bb2 = edge_bits(c0, c1, e);
        int k0 = (bb0 >= 0x80000000u);
        int k1 = (bb1 >= 0xC0000000u);
        int k2 = (bb2 >= 0xE0000000u);
        int dep = k0 ? (k1 ? (k2 ? 3 : 2) : 1) : 0;
        g_ecv[e] = packcv((unsigned)cols[e] | ((unsigned)dep << 28), adj[e]);
    }
    for (int n = gt; n < Nn; n += GT) {
        unsigned bits;
#if PARTITIONABLE
        unsigned o0, o1;
        tf2x32(0u, 7u, 0u, (unsigned)n, o0, o1);
        bits = o0 ^ o1;
#else
        unsigned o0, o1;
        if (n < HALF_N) { tf2x32(0u, 7u, (unsigned)n, (unsigned)(n + HALF_N), o0, o1); bits = o0; }
        else            { tf2x32(0u, 7u, (unsigned)(n - HALF_N), (unsigned)n, o0, o1); bits = o1; }
#endif
        float u = bits_to_uniform(bits);
        float lu = log_acc(u);
        g_gumbel[n] = -log_acc(-lu);
    }
    gridbar(0);

    // Phase B: scan
    __shared__ int sh[GBT];
    int idx = b * CH + tid;
    int v = (tid < CH && idx < Nn) ? g_counts[idx] : 0;
    sh[tid] = v;
    __syncthreads();
#pragma unroll
    for (int off = 1; off < GBT; off <<= 1) {
        int t = (tid >= off) ? sh[tid - off] : 0;
        __syncthreads();
        sh[tid] += t;
        __syncthreads();
    }
    if (tid == GBT - 1) g_bsum[b] = sh[GBT - 1];
    int myincl = sh[tid];
    gridbar(1);
    if (b == 0 && tid == 0) {
        int acc = 0;
        for (int i = 0; i < GB; i++) { g_boff[i] = acc; acc += g_bsum[i]; }
        g_rowptr[Nn] = acc;
    }
    gridbar(2);
    if (tid < CH && idx < Nn) g_rowptr[idx] = g_boff[b] + myincl - v;
    gridbar(3);

    // Phase C: scatter full records (coalesced reads, random 16B store — 1 sector
    // per lane, same as a 4B store; eliminates phase D's per-lane random gather).
    for (int e = gt; e < Ee; e += GT) {
        float2 ecv = g_ecv[e];
        int4 rec;
        rec.x = e;
        rec.y = __float_as_int(ecv.x);
        rec.z = __float_as_int(ecv.y);
        rec.w = 0;
        g_rec[g_rowptr[rows[e]] + g_pos[e]] = rec;
    }
    gridbar(4);

    // Phase D: per-row sort records by eid (payload carried through shuffles);
    // write cv coalesced; orders via deg + ballot/popc (integer-exact).
    int lane = tid & 31;
    int wstride = GT >> 5;
    for (int w = (gt >> 5); w < Nn; w += wstride) {
        int s = g_rowptr[w], t = g_rowptr[w + 1];
        int deg = t - s;
        if (deg <= 32) {
            int eid = 0x7FFFFFFF;
            unsigned pk = 0;
            float v0 = 0.f;
            if (lane < deg) {
                int4 rec = g_rec[s + lane];
                eid = rec.x;
                pk = (unsigned)rec.y;
                v0 = __int_as_float(rec.z);
            }
#pragma unroll
            for (int k = 2; k <= 32; k <<= 1) {
#pragma unroll
                for (int j = k >> 1; j > 0; j >>= 1) {
                    int      oe = __shfl_xor_sync(0xffffffffu, eid, j);
                    unsigned op = __shfl_xor_sync(0xffffffffu, pk, j);
                    float    ov = __shfl_xor_sync(0xffffffffu, v0, j);
                    bool up = ((lane & k) == 0);
                    bool lower = ((lane & j) == 0);
                    bool takeOther = (lower == up) ? (oe < eid) : (oe > eid);
                    if (takeOther) { eid = oe; pk = op; v0 = ov; }
                }
            }
            unsigned dep = pk >> 28;
            if (lane < deg) g_cv[s + lane] = packcv(pk, v0);
            unsigned m1 = __ballot_sync(0xffffffffu, (lane < deg) && (dep >= 1));
            unsigned m2 = __ballot_sync(0xffffffffu, (lane < deg) && (dep >= 2));
            if (lane == 0) {
                g_order0[w] = (float)deg;
                g_order1[w] = (float)__popc(m1);
                g_order2[w] = (float)__popc(m2);
            }
        } else if (lane == 0) {
            // rare fallback: insertion sort of records by eid, in place
            for (int a = s + 1; a < t; a++) {
                int4 x = g_rec[a]; int bb = a - 1;
                while (bb >= s && g_rec[bb].x > x.x) { g_rec[bb + 1] = g_rec[bb]; bb--; }
                g_rec[bb + 1] = x;
            }
            int n1 = 0, n2 = 0;
            for (int q = s; q < t; q++) {
                int4 rec = g_rec[q];
                unsigned dep = ((unsigned)rec.y) >> 28;
                g_cv[q] = packcv((unsigned)rec.y, __int_as_float(rec.z));
                n1 += (dep >= 1);
                n2 += (dep >= 2);
            }
            g_order0[w] = (float)deg;
            g_order1[w] = (float)n1;
            g_order2[w] = (float)n2;
        }
    }
}

// ---------------- propagation ----------------
__global__ void emb0_kernel(const float* __restrict__ X) {
    int w = (blockIdx.x * blockDim.x + threadIdx.x) >> 5;
    int lane = threadIdx.x & 31;
    if (w >= Nn) return;
    int s = g_rowptr[w], t = g_rowptr[w + 1];
    float acc = 0.f;
    int p = s;
    if ((p & 1) && p < t) {
        float2 a = g_cv[p];
        int c = __float_as_int(a.x) & 0x0FFFFFFF;
        acc = __fadd_rn(acc, __fmul_rn(a.y, X[c * Dd + lane]));
        p++;
    }
    for (; p + 8 <= t; p += 8) {
        float4 q0 = *(const float4*)&g_cv[p];
        float4 q1 = *(const float4*)&g_cv[p + 2];
        float4 q2 = *(const float4*)&g_cv[p + 4];
        float4 q3 = *(const float4*)&g_cv[p + 6];
        int c0 = __float_as_int(q0.x) & 0x0FFFFFFF, c1 = __float_as_int(q0.z) & 0x0FFFFFFF;
        int c2 = __float_as_int(q1.x) & 0x0FFFFFFF, c3 = __float_as_int(q1.z) & 0x0FFFFFFF;
        int c4 = __float_as_int(q2.x) & 0x0FFFFFFF, c5 = __float_as_int(q2.z) & 0x0FFFFFFF;
        int c6 = __float_as_int(q3.x) & 0x0FFFFFFF, c7 = __float_as_int(q3.z) & 0x0FFFFFFF;
        float x0 = X[c0 * Dd + lane], x1 = X[c1 * Dd + lane];
        float x2 = X[c2 * Dd + lane], x3 = X[c3 * Dd + lane];
        float x4 = X[c4 * Dd + lane], x5 = X[c5 * Dd + lane];
        float x6 = X[c6 * Dd + lane], x7 = X[c7 * Dd + lane];
        acc = __fadd_rn(acc, __fmul_rn(q0.y, x0));
        acc = __fadd_rn(acc, __fmul_rn(q0.w, x1));
        acc = __fadd_rn(acc, __fmul_rn(q1.y, x2));
        acc = __fadd_rn(acc, __fmul_rn(q1.w, x3));
        acc = __fadd_rn(acc, __fmul_rn(q2.y, x4));
        acc = __fadd_rn(acc, __fmul_rn(q2.w, x5));
        acc = __fadd_rn(acc, __fmul_rn(q3.y, x6));
        acc = __fadd_rn(acc, __fmul_rn(q3.w, x7));
    }
    for (; p < t; p++) {
        float2 a = g_cv[p];
        int c = __float_as_int(a.x) & 0x0FFFFFFF;
        acc = __fadd_rn(acc, __fmul_rn(a.y, X[c * Dd + lane]));
    }
    float e0 = __fsub_rn(acc, X[w * Dd + lane]);
    g_embA[w * Dd + lane] = e0;
    if (lane == 0) g_numA[w] = g_order0[w];
}

// COMP==1: embS01 = e0+e1 stored (register recurrence).
// COMP==2: NO embS/numS writes (iter3 reconstructs from registers).
// COMP==3 (FINAL): embS = ((embS01 + e2) + e3) -- same order as ((e0+e1)+e2)+e3.
template <int SEL, int COMP, int FINAL>
__global__ void iter_kernel(const float* __restrict__ X, float* score_out) {
    const unsigned CThr = ((unsigned)COMP) << 28;
    const float* __restrict__ ord = (COMP == 1) ? g_order0 : ((COMP == 2) ? g_order1 : g_order2);
    const float* __restrict__ cur  = SEL ? g_embB : g_embA;
    float*       __restrict__ nxt  = SEL ? g_embA : g_embB;
    const float* __restrict__ curn = SEL ? g_numB : g_numA;
    float*       __restrict__ nxtn = SEL ? g_numA : g_numB;
    int w = (blockIdx.x * blockDim.x + threadIdx.x) >> 5;
    int lane = threadIdx.x & 31;
    if (w >= Nn) return;
    int s = g_rowptr[w], t = g_rowptr[w + 1];
    float accE = 0.f, accN = 0.f;
    int p = s;
    if ((p & 1) && p < t) {
        float2 a = g_cv[p];
        unsigned pk = __float_as_uint(a.x);
        int c = (int)(pk & 0x0FFFFFFFu);
        float vv = (pk >= CThr) ? a.y : 0.0f;
        accE = __fadd_rn(accE, __fmul_rn(vv, cur[c * Dd + lane]));
        accN = __fadd_rn(accN, __fmul_rn(vv, curn[c]));
        p++;
    }
    for (; p + 8 <= t; p += 8) {
        float4 q0 = *(const float4*)&g_cv[p];
        float4 q1 = *(const float4*)&g_cv[p + 2];
        float4 q2 = *(const float4*)&g_cv[p + 4];
        float4 q3 = *(const float4*)&g_cv[p + 6];
        unsigned p0 = __float_as_uint(q0.x), p1 = __float_as_uint(q0.z);
        unsigned p2 = __float_as_uint(q1.x), p3 = __float_as_uint(q1.z);
        unsigned p4 = __float_as_uint(q2.x), p5 = __float_as_uint(q2.z);
        unsigned p6 = __float_as_uint(q3.x), p7 = __float_as_uint(q3.z);
        int c0 = (int)(p0 & 0x0FFFFFFFu), c1 = (int)(p1 & 0x0FFFFFFFu);
        int c2 = (int)(p2 & 0x0FFFFFFFu), c3 = (int)(p3 & 0x0FFFFFFFu);
        int c4 = (int)(p4 & 0x0FFFFFFFu), c5 = (int)(p5 & 0x0FFFFFFFu);
        int c6 = (int)(p6 & 0x0FFFFFFFu), c7 = (int)(p7 & 0x0FFFFFFFu);
        float v0 = (p0 >= CThr) ? q0.y : 0.0f;
        float v1 = (p1 >= CThr) ? q0.w : 0.0f;
        float v2 = (p2 >= CThr) ? q1.y : 0.0f;
        float v3 = (p3 >= CThr) ? q1.w : 0.0f;
        float v4 = (p4 >= CThr) ? q2.y : 0.0f;
        float v5 = (p5 >= CThr) ? q2.w : 0.0f;
        float v6 = (p6 >= CThr) ? q3.y : 0.0f;
        float v7 = (p7 >= CThr) ? q3.w : 0.0f;
        float x0 = cur[c0 * Dd + lane], x1 = cur[c1 * Dd + lane];
        float x2 = cur[c2 * Dd + lane], x3 = cur[c3 * Dd + lane];
        float x4 = cur[c4 * Dd + lane], x5 = cur[c5 * Dd + lane];
        float x6 = cur[c6 * Dd + lane], x7 = cur[c7 * Dd + lane];
        float n0 = curn[c0], n1 = curn[c1], n2 = curn[c2], n3 = curn[c3];
        float n4 = curn[c4], n5 = curn[c5], n6 = curn[c6], n7 = curn[c7];
        accE = __fadd_rn(accE, __fmul_rn(v0, x0));
        accN = __fadd_rn(accN, __fmul_rn(v0, n0));
        accE = __fadd_rn(accE, __fmul_rn(v1, x1));
        accN = __fadd_rn(accN, __fmul_rn(v1, n1));
        accE = __fadd_rn(accE, __fmul_rn(v2, x2));
        accN = __fadd_rn(accN, __fmul_rn(v2, n2));
        accE = __fadd_rn(accE, __fmul_rn(v3, x3));
        accN = __fadd_rn(accN, __fmul_rn(v3, n3));
        accE = __fadd_rn(accE, __fmul_rn(v4, x4));
        accN = __fadd_rn(accN, __fmul_rn(v4, n4));
        accE = __fadd_rn(accE, __fmul_rn(v5, x5));
        accN = __fadd_rn(accN, __fmul_rn(v5, n5));
        accE = __fadd_rn(accE, __fmul_rn(v6, x6));
        accN = __fadd_rn(accN, __fmul_rn(v6, n6));
        accE = __fadd_rn(accE, __fmul_rn(v7, x7));
        accN = __fadd_rn(accN, __fmul_rn(v7, n7));
    }
    for (; p < t; p++) {
        float2 a = g_cv[p];
        unsigned pk = __float_as_uint(a.x);
        int c = (int)(pk & 0x0FFFFFFFu);
        float vv = (pk >= CThr) ? a.y : 0.0f;
        accE = __fadd_rn(accE, __fmul_rn(vv, cur[c * Dd + lane]));
        accN = __fadd_rn(accN, __fmul_rn(vv, curn[c]));
    }
    float o = ord[w];
    float ce = cur[w * Dd + lane];
    float outE = __fsub_rn(__fsub_rn(accE, ce), __fmul_rn(o, ce));
    float cn = curn[w];
    float outN = __fsub_rn(__fsub_rn(accN, cn), o);

    if (FINAL == 0) {
        nxt[w * Dd + lane] = outE;
        if (lane == 0) nxtn[w] = outN;
        if (COMP == 1) {
            g_embS[w * Dd + lane] = __fadd_rn(ce, outE);     // e0+e1
            if (lane == 0) g_numS[w] = __fadd_rn(cn, outN);  // n0+n1
        }
        // COMP==2: no embS/numS traffic
    } else {
        float embS = __fadd_rn(__fadd_rn(g_embS[w * Dd + lane], ce), outE); // ((e0+e1)+e2)+e3
        float numS = __fadd_rn(__fadd_rn(g_numS[w], cn), outN);
        float den = __fadd_rn(numS, 1e-8f);
        float sv = __fdiv_rn(embS, den);
        float ev = X[w * Dd + lane];

        float p1f = __fmul_rn(sv, sv);
        float sq = 0.f;
#pragma unroll
        for (int d = 0; d < 32; d++) sq = __fadd_rn(sq, __shfl_sync(0xffffffffu, p1f, d));
        float nr = fmaxf(__fsqrt_rn(sq), 1e-12f);

        float p2f = __fmul_rn(ev, ev);
        float sq2 = 0.f;
#pragma unroll
        for (int d = 0; d < 32; d++) sq2 = __fadd_rn(sq2, __shfl_sync(0xffffffffu, p2f, d));
        float nr2 = fmaxf(__fsqrt_rn(sq2), 1e-12f);

        float prod = __fmul_rn(__fdiv_rn(sv, nr), __fdiv_rn(ev, nr2));
        float dot = 0.f;
#pragma unroll
        for (int d = 0; d < 32; d++) dot = __fadd_rn(dot, __shfl_sync(0xffffffffu, prod, d));

        if (lane == 0) {
            float score = __fadd_rn(dot, g_gumbel[w]);
            if (score_out) score_out[w] = score;
            unsigned ub = __float_as_uint(score);
            unsigned key = (ub & 0x80000000u) ? ~ub : (ub | 0x80000000u);
            g_keys[w] = key;
            atomicAdd(&g_hist16[key >> 16], 1u);
        }
    }
}

// ---------------- finish: threshold -> compact -> exact sort ----------------
__global__ void __launch_bounds__(GBT, 1) finish_kernel(float* cand_out) {
    __shared__ unsigned long long sgll[CAND];
    int b = blockIdx.x, tid = threadIdx.x;
    int gt = b * GBT + tid;

    if (b == 0) {
        int* coarse = (int*)sgll;
        int sum = 0;
#pragma unroll 8
        for (int j = 0; j < 64; j++) sum += (int)g_hist16[tid * 64 + j];
        coarse[tid] = sum;
        __syncthreads();
        for (int off = 1; off < 1024; off <<= 1) {
            int v = (tid + off < 1024) ? coarse[tid + off] : 0;
            __syncthreads();
            coarse[tid] += v;
            __syncthreads();
        }
        int mySuf = coarse[tid];
        int nextSuf = (tid + 1 < 1024) ? coarse[tid + 1] : 0;
        if (mySuf >= Kk && nextSuf < Kk) {
            int cum = nextSuf;
            unsigned vbin = (unsigned)(tid * 64);
            for (int bb = 63; bb >= 0; bb--) {
                cum += (int)g_hist16[tid * 64 + bb];
                if (cum >= Kk) { vbin = (unsigned)(tid * 64 + bb); break; }
            }
            g_vbin = vbin;
            g_cntG = 0;
        }
    }
    gridbar(5);

    unsigned vbin = g_vbin;
    for (int i = gt; i < Nn; i += GT) {
        unsigned key = g_keys[i];
        if ((key >> 16) >= vbin) {
            int p = atomicAdd(&g_cntG, 1);
            if (p < CAND) g_cand[p] = (((unsigned long long)(~key)) << 32) | (unsigned)i;
        }
        g_counts[i] = 0;
    }
    if (gt < 5) g_bar[gt] = 0u;
    gridbar(6);
    if (b != 0) return;

    int cnt = g_cntG; if (cnt > CAND) cnt = CAND;
    for (int t = tid; t < CAND; t += GBT)
        sgll[t] = (t < cnt) ? g_cand[t] : 0xFFFFFFFFFFFFFFFFull;
    __syncthreads();
    for (int k = 2; k <= CAND; k <<= 1)
        for (int j = k >> 1; j > 0; j >>= 1) {
            for (int t = tid; t < CAND; t += GBT) {
                int ixj = t ^ j;
                if (ixj > t) {
                    bool up = ((t & k) == 0);
                    unsigned long long a = sgll[t], bb = sgll[ixj];
                    if ((a > bb) == up) { sgll[t] = bb; sgll[ixj] = a; }
                }
            }
            __syncthreads();
        }
    if (tid < Kk && cand_out)
        cand_out[tid] = (float)(int)(sgll[tid] & 0xFFFFFFFFull);
    if (tid < 2) g_bar[5 + tid] = 0u;
}

// ---------------- launch ----------------
extern "C" void kernel_launch(void* const* d_in, const int* in_sizes, int n_in,
                              void* d_out, int out_size) {
    const int*   edge_index = (const int*)d_in[0];
    const float* adj_values = (const float*)d_in[1];
    const float* embeds     = (const float*)d_in[2];
    const int* rows = edge_index;
    const int* cols = edge_index + Ee;
    float* out = (float*)d_out;

    float* score_out = nullptr;
    float* cand_out  = nullptr;
    if (out_size >= Nn + Kk)      { score_out = out; cand_out = out + Nn; }
    else if (out_size == Nn)      { score_out = out; }
    else if (out_size == Kk)      { cand_out = out; }
    else                          { score_out = out; }

    unsigned fk[3][2];
    for (int i = 0; i < 3; i++) tf2x32(0u, 42u, 0u, (unsigned)i, fk[i][0], fk[i][1]);

    const int TB = 256;
    int warpBlocks = (Nn * 32 + TB - 1) / TB;
    build_kernel<<<GB, GBT>>>(rows, cols, adj_values,               // 1 (+gumbel)
                              fk[0][0], fk[0][1],
                              fk[1][0], fk[1][1],
                              fk[2][0], fk[2][1]);
    emb0_kernel<<<warpBlocks, TB>>>(embeds);                        // 2
    iter_kernel<0, 1, 0><<<warpBlocks, TB>>>(nullptr, nullptr);     // 3
    iter_kernel<1, 2, 0><<<warpBlocks, TB>>>(nullptr, nullptr);     // 4 <- ncu window
    iter_kernel<0, 3, 1><<<warpBlocks, TB>>>(embeds, score_out);    // 5 (score + hist)
    finish_kernel<<<GB, GBT>>>(cand_out);                           // 6
}

// round 17
// speedup vs baseline: 1.0641x; 1.0641x over previous
#include <cuda_runtime.h>
#include <math.h>

#define Nn 100000
#define Ee 1600000
#define Dd 32
#define Kk 1024
#define HALF_E (Ee/2)
#define HALF_N (Nn/2)

#define PARTITIONABLE 1

#define GB   148
#define GBT  1024
#define GT   (GB * GBT)
#define CH   ((Nn + GB - 1) / GB)

#define CAND 2048

// ---------------- scratch ----------------
__device__ int      g_counts[Nn];        // zeroed initially + by finish each run
__device__ int      g_rowptr[Nn + 1];
__device__ int      g_pos[Ee];
__device__ __align__(16) float2 g_ecv[Ee]; // (col|dep<<28, v0) in EDGE order
__device__ int      g_eid[Ee];
__device__ __align__(16) float2 g_cv[Ee];  // (pk, v0) in CSR sorted order
__device__ float    g_order0[Nn], g_order1[Nn], g_order2[Nn];
__device__ float    g_embA[Nn * Dd], g_embB[Nn * Dd], g_embS[Nn * Dd];
__device__ float    g_numA[Nn], g_numB[Nn], g_numS[Nn];
__device__ float    g_gumbel[Nn];
__device__ unsigned g_keys[Nn];
__device__ unsigned g_hist16[65536];     // zeroed by build each run
__device__ unsigned g_vbin;
__device__ int      g_cntG;
__device__ unsigned long long g_cand[CAND];
__device__ int      g_bsum[GB];
__device__ int      g_boff[GB];
__device__ unsigned g_bar[8];            // slots 0-4: build; 5-6: finish

// ---------------- threefry-2x32 (JAX schedule) ----------------
__host__ __device__ __forceinline__ void tf2x32(unsigned k0, unsigned k1,
                                                unsigned x0, unsigned x1,
                                                unsigned& o0, unsigned& o1) {
    unsigned k2 = k0 ^ k1 ^ 0x1BD11BDAu;
    x0 += k0; x1 += k1;
#define TFR(r) { x0 += x1; x1 = (x1 << r) | (x1 >> (32 - r)); x1 ^= x0; }
    TFR(13) TFR(15) TFR(26) TFR(6)   x0 += k1; x1 += k2 + 1u;
    TFR(17) TFR(29) TFR(16) TFR(24)  x0 += k2; x1 += k0 + 2u;
    TFR(13) TFR(15) TFR(26) TFR(6)   x0 += k0; x1 += k1 + 3u;
    TFR(17) TFR(29) TFR(16) TFR(24)  x0 += k1; x1 += k2 + 4u;
    TFR(13) TFR(15) TFR(26) TFR(6)   x0 += k2; x1 += k0 + 5u;
#undef TFR
    o0 = x0; o1 = x1;
}

__device__ __forceinline__ float bits_to_uniform(unsigned bits) {
    return __fsub_rn(__uint_as_float((bits >> 9) | 0x3f800000u), 1.0f);
}

__device__ __forceinline__ unsigned edge_bits(unsigned k0, unsigned k1, int e) {
#if PARTITIONABLE
    unsigned o0, o1;
    tf2x32(k0, k1, 0u, (unsigned)e, o0, o1);
    return o0 ^ o1;
#else
    unsigned o0, o1;
    if (e < HALF_E) { tf2x32(k0, k1, (unsigned)e, (unsigned)(e + HALF_E), o0, o1); return o0; }
    else            { tf2x32(k0, k1, (unsigned)(e - HALF_E), (unsigned)e, o0, o1); return o1; }
#endif
}

__device__ __forceinline__ float2 packcv(unsigned pk, float v) {
    float2 r; r.x = __uint_as_float(pk); r.y = v; return r;
}

// ---------------- accurate fp32 natural log (double-float, ~1e-10 rel) ----------------
__device__ float log_acc(float x) {
    if (x == 0.0f) return -INFINITY;
    if (isinf(x)) return INFINITY;
    int ix = __float_as_int(x);
    int e = ((ix >> 23) & 0xFF) - 127;
    float m = __int_as_float((ix & 0x007FFFFF) | 0x3F800000);
    if (m > 1.41421356f) { m *= 0.5f; e += 1; }
    float a = m - 1.0f;
    float bh = m + 1.0f;
    float bl;
    {
        float bp = bh - 1.0f;
        float ap = bh - bp;
        bl = (1.0f - ap) + (m - bp);
    }
    float q0 = a / bh;
    float r  = fmaf(-q0, bh, a);
    r = fmaf(-q0, bl, r);
    float q1 = r / bh;
    float th = q0 * q0;
    float tl = fmaf(q0, q0, -th);
    tl = fmaf(2.0f * q0, q1, tl);
    const float C3H = 0.333333343f;
    const float C3L = -9.93410830e-09f;
    float t2 = th * th;
    float tail = t2 * (0.2f + th * (0.14285714f + th * (0.11111111f +
                 th * (0.090909091f + th * 0.076923077f))));
    float Rh = th * C3H;
    float Rl = fmaf(th, C3H, -Rh);
    Rl += tl * C3H + th * C3L + tail;
    float twq0 = 2.0f * q0;
    float ph = twq0 * Rh;
    float pl = fmaf(twq0, Rh, -ph);
    pl += twq0 * Rl + 2.0f * q1 * Rh;
    float lh = twq0 + ph;
    float z = lh - twq0;
    float ll = (twq0 - (lh - z)) + (ph - z);
    ll += 2.0f * q1 + pl;
    const float LN2H = 0.693145751953125f;
    const float LN2L = 1.4286067653e-06f;
    float fe = (float)e;
    float eh = fe * LN2H;
    float el = fe * LN2L;
    float sh = eh + lh;
    float zz = sh - eh;
    float sl = (eh - (sh - zz)) + (lh - zz);
    return sh + (sl + el + ll);
}

// grid-wide barrier: all GB blocks co-resident (grid == #SMs, occ 1).
__device__ __forceinline__ void gridbar(int id) {
    __syncthreads();
    if (threadIdx.x == 0) {
        __threadfence();
        atomicAdd(&g_bar[id], 1u);
        while (*((volatile unsigned*)&g_bar[id]) < (unsigned)GB) { }
        __threadfence();
    }
    __syncthreads();
}

// ---------------- fused CSR build (+ gumbel) — R15 structure ----------------
__global__ void __launch_bounds__(GBT, 1) build_kernel(
        const int* __restrict__ rows, const int* __restrict__ cols,
        const float* __restrict__ adj,
        unsigned a0, unsigned a1, unsigned b0, unsigned b1,
        unsigned c0, unsigned c1) {
    int b = blockIdx.x, tid = threadIdx.x;
    int gt = b * GBT + tid;

    // Phase A: zero hist16; count (keep position); threefry keeps -> g_ecv; gumbel.
    for (int i = gt; i < 65536; i += GT) g_hist16[i] = 0u;
    for (int e = gt; e < Ee; e += GT) {
        int r = rows[e];
        g_pos[e] = atomicAdd(&g_counts[r], 1);
        unsigned bb0 = edge_bits(a0, a1, e);
        unsigned bb1 = edge_bits(b0, b1, e);
        unsigned bb2 = edge_bits(c0, c1, e);
        int k0 = (bb0 >= 0x80000000u);
        int k1 = (bb1 >= 0xC0000000u);
        int k2 = (bb2 >= 0xE0000000u);
        int dep = k0 ? (k1 ? (k2 ? 3 : 2) : 1) : 0;
        g_ecv[e] = packcv((unsigned)cols[e] | ((unsigned)dep << 28), adj[e]);
    }
    for (int n = gt; n < Nn; n += GT) {
        unsigned bits;
#if PARTITIONABLE
        unsigned o0, o1;
        tf2x32(0u, 7u, 0u, (unsigned)n, o0, o1);
        bits = o0 ^ o1;
#else
        unsigned o0, o1;
        if (n < HALF_N) { tf2x32(0u, 7u, (unsigned)n, (unsigned)(n + HALF_N), o0, o1); bits = o0; }
        else            { tf2x32(0u, 7u, (unsigned)(n - HALF_N), (unsigned)n, o0, o1); bits = o1; }
#endif
        float u = bits_to_uniform(bits);
        float lu = log_acc(u);
        g_gumbel[n] = -log_acc(-lu);
    }
    gridbar(0);

    // Phase B: scan
    __shared__ int sh[GBT];
    int idx = b * CH + tid;
    int v = (tid < CH && idx < Nn) ? g_counts[idx] : 0;
    sh[tid] = v;
    __syncthreads();
#pragma unroll
    for (int off = 1; off < GBT; off <<= 1) {
        int t = (tid >= off) ? sh[tid - off] : 0;
        __syncthreads();
        sh[tid] += t;
        __syncthreads();
    }
    if (tid == GBT - 1) g_bsum[b] = sh[GBT - 1];
    int myincl = sh[tid];
    gridbar(1);
    if (b == 0 && tid == 0) {
        int acc = 0;
        for (int i = 0; i < GB; i++) { g_boff[i] = acc; acc += g_bsum[i]; }
        g_rowptr[Nn] = acc;
    }
    gridbar(2);
    if (tid < CH && idx < Nn) g_rowptr[idx] = g_boff[b] + myincl - v;
    gridbar(3);

    // Phase C: scatter 4B eid only (byte-minimal random store)
    for (int e = gt; e < Ee; e += GT) {
        g_eid[g_rowptr[rows[e]] + g_pos[e]] = e;
    }
    gridbar(4);

    // Phase D: per-row eid sort + single 8B gather per edge; orders via ballot/popc
    // (integer-exact: adj==1 and keeps are {0,1} -> sums are small exact ints).
    int lane = tid & 31;
    int wstride = GT >> 5;
    for (int w = (gt >> 5); w < Nn; w += wstride) {
        int s = g_rowptr[w], t = g_rowptr[w + 1];
        int deg = t - s;
        if (deg <= 32) {
            int eid = (lane < deg) ? g_eid[s + lane] : 0x7FFFFFFF;
#pragma unroll
            for (int k = 2; k <= 32; k <<= 1) {
#pragma unroll
                for (int j = k >> 1; j > 0; j >>= 1) {
                    int other = __shfl_xor_sync(0xffffffffu, eid, j);
                    bool up = ((lane & k) == 0);
                    bool lower = ((lane & j) == 0);
                    int mn = min(eid, other), mx = max(eid, other);
                    eid = (lower == up) ? mn : mx;
                }
            }
            unsigned dep = 0;
            if (lane < deg) {
                float2 ecv = g_ecv[eid];
                dep = __float_as_uint(ecv.x) >> 28;
                g_cv[s + lane] = ecv;
            }
            unsigned m1 = __ballot_sync(0xffffffffu, (lane < deg) && (dep >= 1));
            unsigned m2 = __ballot_sync(0xffffffffu, (lane < deg) && (dep >= 2));
            if (lane == 0) {
                g_order0[w] = (float)deg;
                g_order1[w] = (float)__popc(m1);
                g_order2[w] = (float)__popc(m2);
            }
        } else if (lane == 0) {
            for (int a = s + 1; a < t; a++) {
                int x = g_eid[a]; int bb = a - 1;
                while (bb >= s && g_eid[bb] > x) { g_eid[bb + 1] = g_eid[bb]; bb--; }
                g_eid[bb + 1] = x;
            }
            int n1 = 0, n2 = 0;
            for (int q = s; q < t; q++) {
                float2 ecv = g_ecv[g_eid[q]];
                unsigned dep = __float_as_uint(ecv.x) >> 28;
                g_cv[q] = ecv;
                n1 += (dep >= 1);
                n2 += (dep >= 2);
            }
            g_order0[w] = (float)deg;
            g_order1[w] = (float)n1;
            g_order2[w] = (float)n2;
        }
    }
}

// ---------------- propagation ----------------
__global__ void emb0_kernel(const float* __restrict__ X) {
    int w = (blockIdx.x * blockDim.x + threadIdx.x) >> 5;
    int lane = threadIdx.x & 31;
    if (w >= Nn) return;
    int s = g_rowptr[w], t = g_rowptr[w + 1];
    float acc = 0.f;
    int p = s;
    if ((p & 1) && p < t) {
        float2 a = g_cv[p];
        int c = __float_as_int(a.x) & 0x0FFFFFFF;
        acc = __fadd_rn(acc, __fmul_rn(a.y, X[c * Dd + lane]));
        p++;
    }
    for (; p + 8 <= t; p += 8) {
        float4 q0 = *(const float4*)&g_cv[p];
        float4 q1 = *(const float4*)&g_cv[p + 2];
        float4 q2 = *(const float4*)&g_cv[p + 4];
        float4 q3 = *(const float4*)&g_cv[p + 6];
        int c0 = __float_as_int(q0.x) & 0x0FFFFFFF, c1 = __float_as_int(q0.z) & 0x0FFFFFFF;
        int c2 = __float_as_int(q1.x) & 0x0FFFFFFF, c3 = __float_as_int(q1.z) & 0x0FFFFFFF;
        int c4 = __float_as_int(q2.x) & 0x0FFFFFFF, c5 = __float_as_int(q2.z) & 0x0FFFFFFF;
        int c6 = __float_as_int(q3.x) & 0x0FFFFFFF, c7 = __float_as_int(q3.z) & 0x0FFFFFFF;
        float x0 = X[c0 * Dd + lane], x1 = X[c1 * Dd + lane];
        float x2 = X[c2 * Dd + lane], x3 = X[c3 * Dd + lane];
        float x4 = X[c4 * Dd + lane], x5 = X[c5 * Dd + lane];
        float x6 = X[c6 * Dd + lane], x7 = X[c7 * Dd + lane];
        acc = __fadd_rn(acc, __fmul_rn(q0.y, x0));
        acc = __fadd_rn(acc, __fmul_rn(q0.w, x1));
        acc = __fadd_rn(acc, __fmul_rn(q1.y, x2));
        acc = __fadd_rn(acc, __fmul_rn(q1.w, x3));
        acc = __fadd_rn(acc, __fmul_rn(q2.y, x4));
        acc = __fadd_rn(acc, __fmul_rn(q2.w, x5));
        acc = __fadd_rn(acc, __fmul_rn(q3.y, x6));
        acc = __fadd_rn(acc, __fmul_rn(q3.w, x7));
    }
    for (; p < t; p++) {
        float2 a = g_cv[p];
        int c = __float_as_int(a.x) & 0x0FFFFFFF;
        acc = __fadd_rn(acc, __fmul_rn(a.y, X[c * Dd + lane]));
    }
    float e0 = __fsub_rn(acc, X[w * Dd + lane]);
    g_embA[w * Dd + lane] = e0;
    if (lane == 0) g_numA[w] = g_order0[w];
}

// COMP==1: embS01 = e0+e1 stored (register recurrence).
// COMP==2: NO embS/numS writes (iter3 reconstructs from registers).
// COMP==3 (FINAL): embS = ((embS01 + e2) + e3) -- same order as ((e0+e1)+e2)+e3.
template <int SEL, int COMP, int FINAL>
__global__ void iter_kernel(const float* __restrict__ X, float* score_out) {
    const unsigned CThr = ((unsigned)COMP) << 28;
    const float* __restrict__ ord = (COMP == 1) ? g_order0 : ((COMP == 2) ? g_order1 : g_order2);
    const float* __restrict__ cur  = SEL ? g_embB : g_embA;
    float*       __restrict__ nxt  = SEL ? g_embA : g_embB;
    const float* __restrict__ curn = SEL ? g_numB : g_numA;
    float*       __restrict__ nxtn = SEL ? g_numA : g_numB;
    int w = (blockIdx.x * blockDim.x + threadIdx.x) >> 5;
    int lane = threadIdx.x & 31;
    if (w >= Nn) return;
    int s = g_rowptr[w], t = g_rowptr[w + 1];
    float accE = 0.f, accN = 0.f;
    int p = s;
    if ((p & 1) && p < t) {
        float2 a = g_cv[p];
        unsigned pk = __float_as_uint(a.x);
        int c = (int)(pk & 0x0FFFFFFFu);
        float vv = (pk >= CThr) ? a.y : 0.0f;
        accE = __fadd_rn(accE, __fmul_rn(vv, cur[c * Dd + lane]));
        accN = __fadd_rn(accN, __fmul_rn(vv, curn[c]));
        p++;
    }
    for (; p + 8 <= t; p += 8) {
        float4 q0 = *(const float4*)&g_cv[p];
        float4 q1 = *(const float4*)&g_cv[p + 2];
        float4 q2 = *(const float4*)&g_cv[p + 4];
        float4 q3 = *(const float4*)&g_cv[p + 6];
        unsigned p0 = __float_as_uint(q0.x), p1 = __float_as_uint(q0.z);
        unsigned p2 = __float_as_uint(q1.x), p3 = __float_as_uint(q1.z);
        unsigned p4 = __float_as_uint(q2.x), p5 = __float_as_uint(q2.z);
        unsigned p6 = __float_as_uint(q3.x), p7 = __float_as_uint(q3.z);
        int c0 = (int)(p0 & 0x0FFFFFFFu), c1 = (int)(p1 & 0x0FFFFFFFu);
        int c2 = (int)(p2 & 0x0FFFFFFFu), c3 = (int)(p3 & 0x0FFFFFFFu);
        int c4 = (int)(p4 & 0x0FFFFFFFu), c5 = (int)(p5 & 0x0FFFFFFFu);
        int c6 = (int)(p6 & 0x0FFFFFFFu), c7 = (int)(p7 & 0x0FFFFFFFu);
        float v0 = (p0 >= CThr) ? q0.y : 0.0f;
        float v1 = (p1 >= CThr) ? q0.w : 0.0f;
        float v2 = (p2 >= CThr) ? q1.y : 0.0f;
        float v3 = (p3 >= CThr) ? q1.w : 0.0f;
        float v4 = (p4 >= CThr) ? q2.y : 0.0f;
        float v5 = (p5 >= CThr) ? q2.w : 0.0f;
        float v6 = (p6 >= CThr) ? q3.y : 0.0f;
        float v7 = (p7 >= CThr) ? q3.w : 0.0f;
        float x0 = cur[c0 * Dd + lane], x1 = cur[c1 * Dd + lane];
        float x2 = cur[c2 * Dd + lane], x3 = cur[c3 * Dd + lane];
        float x4 = cur[c4 * Dd + lane], x5 = cur[c5 * Dd + lane];
        float x6 = cur[c6 * Dd + lane], x7 = cur[c7 * Dd + lane];
        float n0 = curn[c0], n1 = curn[c1], n2 = curn[c2], n3 = curn[c3];
        float n4 = curn[c4], n5 = curn[c5], n6 = curn[c6], n7 = curn[c7];
        accE = __fadd_rn(accE, __fmul_rn(v0, x0));
        accN = __fadd_rn(accN, __fmul_rn(v0, n0));
        accE = __fadd_rn(accE, __fmul_rn(v1, x1));
        accN = __fadd_rn(accN, __fmul_rn(v1, n1));
        accE = __fadd_rn(accE, __fmul_rn(v2, x2));
        accN = __fadd_rn(accN, __fmul_rn(v2, n2));
        accE = __fadd_rn(accE, __fmul_rn(v3, x3));
        accN = __fadd_rn(accN, __fmul_rn(v3, n3));
        accE = __fadd_rn(accE, __fmul_rn(v4, x4));
        accN = __fadd_rn(accN, __fmul_rn(v4, n4));
        accE = __fadd_rn(accE, __fmul_rn(v5, x5));
        accN = __fadd_rn(accN, __fmul_rn(v5, n5));
        accE = __fadd_rn(accE, __fmul_rn(v6, x6));
        accN = __fadd_rn(accN, __fmul_rn(v6, n6));
        accE = __fadd_rn(accE, __fmul_rn(v7, x7));
        accN = __fadd_rn(accN, __fmul_rn(v7, n7));
    }
    for (; p < t; p++) {
        float2 a = g_cv[p];
        unsigned pk = __float_as_uint(a.x);
        int c = (int)(pk & 0x0FFFFFFFu);
        float vv = (pk >= CThr) ? a.y : 0.0f;
        accE = __fadd_rn(accE, __fmul_rn(vv, cur[c * Dd + lane]));
        accN = __fadd_rn(accN, __fmul_rn(vv, curn[c]));
    }
    float o = ord[w];
    float ce = cur[w * Dd + lane];
    float outE = __fsub_rn(__fsub_rn(accE, ce), __fmul_rn(o, ce));
    float cn = curn[w];
    float outN = __fsub_rn(__fsub_rn(accN, cn), o);

    if (FINAL == 0) {
        nxt[w * Dd + lane] = outE;
        if (lane == 0) nxtn[w] = outN;
        if (COMP == 1) {
            g_embS[w * Dd + lane] = __fadd_rn(ce, outE);     // e0+e1
            if (lane == 0) g_numS[w] = __fadd_rn(cn, outN);  // n0+n1
        }
        // COMP==2: no embS/numS traffic
    } else {
        float embS = __fadd_rn(__fadd_rn(g_embS[w * Dd + lane], ce), outE); // ((e0+e1)+e2)+e3
        float numS = __fadd_rn(__fadd_rn(g_numS[w], cn), outN);
        float den = __fadd_rn(numS, 1e-8f);
        float sv = __fdiv_rn(embS, den);
        float ev = X[w * Dd + lane];

        float p1f = __fmul_rn(sv, sv);
        float sq = 0.f;
#pragma unroll
        for (int d = 0; d < 32; d++) sq = __fadd_rn(sq, __shfl_sync(0xffffffffu, p1f, d));
        float nr = fmaxf(__fsqrt_rn(sq), 1e-12f);

        float p2f = __fmul_rn(ev, ev);
        float sq2 = 0.f;
#pragma unroll
        for (int d = 0; d < 32; d++) sq2 = __fadd_rn(sq2, __shfl_sync(0xffffffffu, p2f, d));
        float nr2 = fmaxf(__fsqrt_rn(sq2), 1e-12f);

        float prod = __fmul_rn(__fdiv_rn(sv, nr), __fdiv_rn(ev, nr2));
        float dot = 0.f;
#pragma unroll
        for (int d = 0; d < 32; d++) dot = __fadd_rn(dot, __shfl_sync(0xffffffffu, prod, d));

        if (lane == 0) {
            float score = __fadd_rn(dot, g_gumbel[w]);
            if (score_out) score_out[w] = score;
            unsigned ub = __float_as_uint(score);
            unsigned key = (ub & 0x80000000u) ? ~ub : (ub | 0x80000000u);
            g_keys[w] = key;
            atomicAdd(&g_hist16[key >> 16], 1u);
        }
    }
}

// ---------------- finish: threshold -> compact -> exact sort ----------------
__global__ void __launch_bounds__(GBT, 1) finish_kernel(float* cand_out) {
    __shared__ unsigned long long sgll[CAND];
    int b = blockIdx.x, tid = threadIdx.x;
    int gt = b * GBT + tid;

    if (b == 0) {
        int* coarse = (int*)sgll;
        int sum = 0;
#pragma unroll 8
        for (int j = 0; j < 64; j++) sum += (int)g_hist16[tid * 64 + j];
        coarse[tid] = sum;
        __syncthreads();
        for (int off = 1; off < 1024; off <<= 1) {
            int v = (tid + off < 1024) ? coarse[tid + off] : 0;
            __syncthreads();
            coarse[tid] += v;
            __syncthreads();
        }
        int mySuf = coarse[tid];
        int nextSuf = (tid + 1 < 1024) ? coarse[tid + 1] : 0;
        if (mySuf >= Kk && nextSuf < Kk) {
            int cum = nextSuf;
            unsigned vbin = (unsigned)(tid * 64);
            for (int bb = 63; bb >= 0; bb--) {
                cum += (int)g_hist16[tid * 64 + bb];
                if (cum >= Kk) { vbin = (unsigned)(tid * 64 + bb); break; }
            }
            g_vbin = vbin;
            g_cntG = 0;
        }
    }
    gridbar(5);

    unsigned vbin = g_vbin;
    for (int i = gt; i < Nn; i += GT) {
        unsigned key = g_keys[i];
        if ((key >> 16) >= vbin) {
            int p = atomicAdd(&g_cntG, 1);
            if (p < CAND) g_cand[p] = (((unsigned long long)(~key)) << 32) | (unsigned)i;
        }
        g_counts[i] = 0;
    }
    if (gt < 5) g_bar[gt] = 0u;
    gridbar(6);
    if (b != 0) return;

    int cnt = g_cntG; if (cnt > CAND) cnt = CAND;
    for (int t = tid; t < CAND; t += GBT)
        sgll[t] = (t < cnt) ? g_cand[t] : 0xFFFFFFFFFFFFFFFFull;
    __syncthreads();
    for (int k = 2; k <= CAND; k <<= 1)
        for (int j = k >> 1; j > 0; j >>= 1) {
            for (int t = tid; t < CAND; t += GBT) {
                int ixj = t ^ j;
                if (ixj > t) {
                    bool up = ((t & k) == 0);
                    unsigned long long a = sgll[t], bb = sgll[ixj];
                    if ((a > bb) == up) { sgll[t] = bb; sgll[ixj] = a; }
                }
            }
            __syncthreads();
        }
    if (tid < Kk && cand_out)
        cand_out[tid] = (float)(int)(sgll[tid] & 0xFFFFFFFFull);
    if (tid < 2) g_bar[5 + tid] = 0u;
}

// ---------------- launch ----------------
extern "C" void kernel_launch(void* const* d_in, const int* in_sizes, int n_in,
                              void* d_out, int out_size) {
    const int*   edge_index = (const int*)d_in[0];
    const float* adj_values = (const float*)d_in[1];
    const float* embeds     = (const float*)d_in[2];
    const int* rows = edge_index;
    const int* cols = edge_index + Ee;
    float* out = (float*)d_out;

    float* score_out = nullptr;
    float* cand_out  = nullptr;
    if (out_size >= Nn + Kk)      { score_out = out; cand_out = out + Nn; }
    else if (out_size == Nn)      { score_out = out; }
    else if (out_size == Kk)      { cand_out = out; }
    else                          { score_out = out; }

    unsigned fk[3][2];
    for (int i = 0; i < 3; i++) tf2x32(0u, 42u, 0u, (unsigned)i, fk[i][0], fk[i][1]);

    const int TB = 256;
    int warpBlocks = (Nn * 32 + TB - 1) / TB;
    build_kernel<<<GB, GBT>>>(rows, cols, adj_values,               // 1 (+gumbel)
                              fk[0][0], fk[0][1],
                              fk[1][0], fk[1][1],
                              fk[2][0], fk[2][1]);
    emb0_kernel<<<warpBlocks, TB>>>(embeds);                        // 2
    iter_kernel<0, 1, 0><<<warpBlocks, TB>>>(nullptr, nullptr);     // 3
    iter_kernel<1, 2, 0><<<warpBlocks, TB>>>(nullptr, nullptr);     // 4 <- ncu window
    iter_kernel<0, 3, 1><<<warpBlocks, TB>>>(embeds, score_out);    // 5 (score + hist)
    finish_kernel<<<GB, GBT>>>(cand_out);                           // 6
}